// round 13
// baseline (speedup 1.0000x reference)
#include <cuda_runtime.h>
#include <cuda_bf16.h>
#include <math.h>
#include <stdint.h>

// Problem constants
#define BB 2
#define SS 2048
#define DD 512
#define HH 8
#define NT (BB*SS)     // 4096 tokens
#define FFDIM 2048
#define TV 1000
#define NLAYER 2

// ---------------- scratch ------------------------------------------------------
__device__ float g_h[NT*DD];
__device__ float g_a[NT*DD];
__device__ float g_qkv[3][NT*DD];
__device__ float g_t[NT*DD];
__device__ float g_f[NT*FFDIM];

// ---------------- tf32 helpers (GEMM path) -------------------------------------
__device__ __forceinline__ uint32_t f2tf(float x) {
    uint32_t r; asm("cvt.rna.tf32.f32 %0, %1;" : "=r"(r) : "f"(x)); return r;
}
__device__ __forceinline__ void mma8(float* c,
                                     uint32_t a0, uint32_t a1, uint32_t a2, uint32_t a3,
                                     uint32_t b0, uint32_t b1) {
    asm volatile("mma.sync.aligned.m16n8k8.row.col.f32.tf32.tf32.f32 "
                 "{%0,%1,%2,%3}, {%4,%5,%6,%7}, {%8,%9}, {%0,%1,%2,%3};"
                 : "+f"(c[0]), "+f"(c[1]), "+f"(c[2]), "+f"(c[3])
                 : "r"(a0), "r"(a1), "r"(a2), "r"(a3), "r"(b0), "r"(b1));
}

// ---------------- bf16 helpers -------------------------------------------------
__device__ __forceinline__ uint32_t pk2(float lo, float hi) {
    uint32_t r;
    asm("cvt.rn.bf16x2.f32 %0, %1, %2;" : "=r"(r) : "f"(hi), "f"(lo));
    return r;
}
__device__ __forceinline__ void mma16(float* c,
                                      uint32_t a0, uint32_t a1, uint32_t a2, uint32_t a3,
                                      uint32_t b0, uint32_t b1) {
    asm volatile("mma.sync.aligned.m16n8k16.row.col.f32.bf16.bf16.f32 "
                 "{%0,%1,%2,%3}, {%4,%5,%6,%7}, {%8,%9}, {%0,%1,%2,%3};"
                 : "+f"(c[0]), "+f"(c[1]), "+f"(c[2]), "+f"(c[3])
                 : "r"(a0), "r"(a1), "r"(a2), "r"(a3), "r"(b0), "r"(b1));
}
__device__ __forceinline__ uint32_t sptr(const void* p) {
    return (uint32_t)__cvta_generic_to_shared(p);
}
__device__ __forceinline__ void ldsm_x4(uint32_t& r0, uint32_t& r1,
                                        uint32_t& r2, uint32_t& r3, uint32_t addr) {
    asm volatile("ldmatrix.sync.aligned.m8n8.x4.shared.b16 {%0,%1,%2,%3}, [%4];"
                 : "=r"(r0), "=r"(r1), "=r"(r2), "=r"(r3) : "r"(addr));
}

// ---------------- embedding + sinusoidal positional ---------------------------
__global__ void embed_kernel(const int* __restrict__ ids,
                             const float* __restrict__ emb,
                             float* __restrict__ h) {
    int idx = blockIdx.x * blockDim.x + threadIdx.x;
    if (idx >= NT*DD) return;
    int d   = idx & (DD-1);
    int tok = idx >> 9;
    int s   = tok & (SS-1);
    int id  = ids[tok];

    double pos;
    if (d < DD/2) {
        double inv = exp(-(2.0*d/(double)DD) * log(10000.0));
        pos = sin((double)s * inv);
    } else {
        int i = d - DD/2;
        double inv = exp(-(2.0*i/(double)DD) * log(10000.0));
        pos = cos((double)s * inv);
    }
    h[idx] = emb[id*DD + d] + (float)pos;
}

// ---------------- LayerNorm ----------------------------------------------------
__global__ void ln_kernel(const float* __restrict__ x,
                          const float* __restrict__ sc,
                          const float* __restrict__ bi,
                          float* __restrict__ y) {
    __shared__ float redA[4];
    __shared__ float redB[4];
    int row = blockIdx.x;
    int tid = threadIdx.x;
    const float* xr = x + row*DD;

    float v[4];
    float s = 0.f;
#pragma unroll
    for (int i = 0; i < 4; ++i) { v[i] = xr[tid + i*128]; s += v[i]; }
#pragma unroll
    for (int o = 16; o > 0; o >>= 1) s += __shfl_xor_sync(0xffffffffu, s, o);
    if ((tid & 31) == 0) redA[tid >> 5] = s;
    __syncthreads();
    float mean = (redA[0] + redA[1] + redA[2] + redA[3]) * (1.f/DD);

    float vs = 0.f;
#pragma unroll
    for (int i = 0; i < 4; ++i) { float d0 = v[i] - mean; vs += d0*d0; }
#pragma unroll
    for (int o = 16; o > 0; o >>= 1) vs += __shfl_xor_sync(0xffffffffu, vs, o);
    if ((tid & 31) == 0) redB[tid >> 5] = vs;
    __syncthreads();
    float var = (redB[0] + redB[1] + redB[2] + redB[3]) * (1.f/DD);
    float inv = rsqrtf(var + 1e-3f);

#pragma unroll
    for (int i = 0; i < 4; ++i) {
        int d0 = tid + i*128;
        y[row*DD + d0] = (v[i] - mean) * inv * sc[d0] + bi[d0];
    }
}

// ---------------- tf32 tensor-core GEMM body -----------------------------------
// BM=128 BN=64 BK=32. 256 threads = 8 warps (4M x 2N); warp tile 32x32.
#define GLDA 36
#define GLDB 68
template<bool USE_BIAS, bool RELU, bool ACC>
__device__ __forceinline__ void gemm_body(
        const float* __restrict__ A, const float* __restrict__ B,
        const float* __restrict__ bias, float* __restrict__ C,
        int M, int N, int K, int m0, int n0) {
    __shared__ uint32_t As[128*GLDA];
    __shared__ uint32_t Bs[32*GLDB];
    int tid = threadIdx.x;
    int warp = tid >> 5, lane = tid & 31;
    int wm = warp >> 1, wn = warp & 1;
    int g = lane >> 2, t = lane & 3;

    int ar = tid >> 3,  akq = (tid & 7) * 4;
    int br = tid >> 4,  bnq = (tid & 15) * 4;

    float4 pa[4];
    float4 pb[2];

    auto load_g = [&](int k0) {
#pragma unroll
        for (int i = 0; i < 4; ++i)
            pa[i] = *reinterpret_cast<const float4*>(&A[(long)(m0 + ar + i*32)*K + k0 + akq]);
#pragma unroll
        for (int i = 0; i < 2; ++i) {
            int col = n0 + bnq;
            long rowoff = (long)(k0 + br + i*16)*N;
            if (col + 3 < N) {
                pb[i] = *reinterpret_cast<const float4*>(&B[rowoff + col]);
            } else {
                float e[4];
#pragma unroll
                for (int j = 0; j < 4; ++j)
                    e[j] = (col + j < N) ? B[rowoff + col + j] : 0.f;
                pb[i] = make_float4(e[0], e[1], e[2], e[3]);
            }
        }
    };
    auto sts = [&]() {
#pragma unroll
        for (int i = 0; i < 4; ++i) {
            uint32_t* p = &As[(ar + i*32)*GLDA + akq];
            p[0] = f2tf(pa[i].x); p[1] = f2tf(pa[i].y);
            p[2] = f2tf(pa[i].z); p[3] = f2tf(pa[i].w);
        }
#pragma unroll
        for (int i = 0; i < 2; ++i) {
            uint32_t* p = &Bs[(br + i*16)*GLDB + bnq];
            p[0] = f2tf(pb[i].x); p[1] = f2tf(pb[i].y);
            p[2] = f2tf(pb[i].z); p[3] = f2tf(pb[i].w);
        }
    };

    float c[2][4][4];
#pragma unroll
    for (int mt = 0; mt < 2; ++mt)
#pragma unroll
        for (int nt = 0; nt < 4; ++nt)
#pragma unroll
            for (int j = 0; j < 4; ++j) c[mt][nt][j] = 0.f;

    int nk = K >> 5;
    load_g(0);
    sts();
    __syncthreads();

    for (int it = 0; it < nk; ++it) {
        if (it + 1 < nk) load_g((it + 1) << 5);

        int rbw = wm*32, nbw = wn*32;
#pragma unroll
        for (int ks = 0; ks < 4; ++ks) {
            int kk = ks * 8;
            uint32_t a[2][4], b[4][2];
#pragma unroll
            for (int mt = 0; mt < 2; ++mt) {
                int rb = rbw + mt*16;
                a[mt][0] = As[(rb + g    )*GLDA + kk + t];
                a[mt][1] = As[(rb + g + 8)*GLDA + kk + t];
                a[mt][2] = As[(rb + g    )*GLDA + kk + t + 4];
                a[mt][3] = As[(rb + g + 8)*GLDA + kk + t + 4];
            }
#pragma unroll
            for (int nt = 0; nt < 4; ++nt) {
                int nb = nbw + nt*8;
                b[nt][0] = Bs[(kk + t    )*GLDB + nb + g];
                b[nt][1] = Bs[(kk + t + 4)*GLDB + nb + g];
            }
#pragma unroll
            for (int mt = 0; mt < 2; ++mt)
#pragma unroll
                for (int nt = 0; nt < 4; ++nt)
                    mma8(c[mt][nt], a[mt][0], a[mt][1], a[mt][2], a[mt][3],
                         b[nt][0], b[nt][1]);
        }
        if (it + 1 < nk) {
            __syncthreads();
            sts();
            __syncthreads();
        }
    }

#pragma unroll
    for (int mt = 0; mt < 2; ++mt) {
#pragma unroll
        for (int nt = 0; nt < 4; ++nt) {
            int row0 = m0 + wm*32 + mt*16 + g;
            int col  = n0 + wn*32 + nt*8 + 2*t;
            if (col < N) {
                float b0 = 0.f, b1 = 0.f;
                if (USE_BIAS) { b0 = bias[col]; b1 = bias[col + 1]; }
#pragma unroll
                for (int half = 0; half < 2; ++half) {
                    int row = row0 + half*8;
                    float v0 = c[mt][nt][half*2 + 0] + b0;
                    float v1 = c[mt][nt][half*2 + 1] + b1;
                    if (RELU) { v0 = fmaxf(v0, 0.f); v1 = fmaxf(v1, 0.f); }
                    float* cp = &C[(long)row*N + col];
                    if (ACC) { v0 += cp[0]; v1 += cp[1]; }
                    cp[0] = v0; cp[1] = v1;
                }
            }
        }
    }
}

template<bool USE_BIAS, bool RELU, bool ACC>
__global__ __launch_bounds__(256, 2) void mma_gemm(
        const float* __restrict__ A, const float* __restrict__ B,
        const float* __restrict__ bias, float* __restrict__ C,
        int M, int N, int K) {
    gemm_body<USE_BIAS, RELU, ACC>(A, B, bias, C, M, N, K,
                                   blockIdx.y * 128, blockIdx.x * 64);
}

__global__ __launch_bounds__(256, 2) void mma_gemm_qkv(
        const float* __restrict__ A,
        const float* __restrict__ Bq, const float* __restrict__ Bk,
        const float* __restrict__ Bv, float* __restrict__ Cbase,
        int M, int N, int K) {
    int z = blockIdx.z;
    const float* B = (z == 0) ? Bq : (z == 1) ? Bk : Bv;
    float* C = Cbase + (long)z * NT * DD;
    gemm_body<false, false, false>(A, B, nullptr, C, M, N, K,
                                   blockIdx.y * 128, blockIdx.x * 64);
}

// ---------------- bf16 tensor-core GEMM body (FFN) -----------------------------
// BM=128 BN=64 BK=32 (=16 kwords). Same warp layout as tf32 body.
#define BLDA 20
#define BLDB 20
template<bool USE_BIAS, bool RELU, bool ACC>
__device__ __forceinline__ void gemm_body_bf(
        const float* __restrict__ A, const float* __restrict__ B,
        const float* __restrict__ bias, float* __restrict__ C,
        int M, int N, int K, int m0, int n0) {
    __shared__ uint32_t As[128*BLDA];
    __shared__ uint32_t Bs[64*BLDB];
    int tid = threadIdx.x;
    int warp = tid >> 5, lane = tid & 31;
    int wm = warp >> 1, wn = warp & 1;
    int g = lane >> 2, t = lane & 3;

    int ar = tid >> 3, aw = (tid & 7) * 2;
    int br = tid & 15, bc = (tid >> 4) * 4;

    float4 pa[4];
    float4 pb0, pb1;

    auto load_g = [&](int k0) {
#pragma unroll
        for (int i = 0; i < 4; ++i)
            pa[i] = *reinterpret_cast<const float4*>(&A[(long)(m0 + ar + i*32)*K + k0 + aw*2]);
        long r0 = (long)(k0 + 2*br)*N, r1 = r0 + N;
        int col = n0 + bc;
        pb0 = *reinterpret_cast<const float4*>(&B[r0 + col]);
        pb1 = *reinterpret_cast<const float4*>(&B[r1 + col]);
    };
    auto sts = [&]() {
#pragma unroll
        for (int i = 0; i < 4; ++i) {
            uint32_t* p = &As[(ar + i*32)*BLDA + aw];
            p[0] = pk2(pa[i].x, pa[i].y);
            p[1] = pk2(pa[i].z, pa[i].w);
        }
        Bs[(bc + 0)*BLDB + br] = pk2(pb0.x, pb1.x);
        Bs[(bc + 1)*BLDB + br] = pk2(pb0.y, pb1.y);
        Bs[(bc + 2)*BLDB + br] = pk2(pb0.z, pb1.z);
        Bs[(bc + 3)*BLDB + br] = pk2(pb0.w, pb1.w);
    };

    float c[2][4][4];
#pragma unroll
    for (int mt = 0; mt < 2; ++mt)
#pragma unroll
        for (int nt = 0; nt < 4; ++nt)
#pragma unroll
            for (int j = 0; j < 4; ++j) c[mt][nt][j] = 0.f;

    int nk = K >> 5;
    load_g(0);
    sts();
    __syncthreads();

    for (int it = 0; it < nk; ++it) {
        if (it + 1 < nk) load_g((it + 1) << 5);

        int rbw = wm*32, nbw = wn*32;
#pragma unroll
        for (int ks = 0; ks < 2; ++ks) {
            int kk = ks * 8;
            uint32_t a[2][4], b[4][2];
#pragma unroll
            for (int mt = 0; mt < 2; ++mt) {
                int rb = rbw + mt*16;
                a[mt][0] = As[(rb + g    )*BLDA + kk + t];
                a[mt][1] = As[(rb + g + 8)*BLDA + kk + t];
                a[mt][2] = As[(rb + g    )*BLDA + kk + t + 4];
                a[mt][3] = As[(rb + g + 8)*BLDA + kk + t + 4];
            }
#pragma unroll
            for (int nt = 0; nt < 4; ++nt) {
                int nb = nbw + nt*8;
                b[nt][0] = Bs[(nb + g)*BLDB + kk + t];
                b[nt][1] = Bs[(nb + g)*BLDB + kk + t + 4];
            }
#pragma unroll
            for (int mt = 0; mt < 2; ++mt)
#pragma unroll
                for (int nt = 0; nt < 4; ++nt)
                    mma16(c[mt][nt], a[mt][0], a[mt][1], a[mt][2], a[mt][3],
                          b[nt][0], b[nt][1]);
        }
        if (it + 1 < nk) {
            __syncthreads();
            sts();
            __syncthreads();
        }
    }

#pragma unroll
    for (int mt = 0; mt < 2; ++mt) {
#pragma unroll
        for (int nt = 0; nt < 4; ++nt) {
            int row0 = m0 + wm*32 + mt*16 + g;
            int col  = n0 + wn*32 + nt*8 + 2*t;
            float b0 = 0.f, b1 = 0.f;
            if (USE_BIAS) { b0 = bias[col]; b1 = bias[col + 1]; }
#pragma unroll
            for (int half = 0; half < 2; ++half) {
                int row = row0 + half*8;
                float v0 = c[mt][nt][half*2 + 0] + b0;
                float v1 = c[mt][nt][half*2 + 1] + b1;
                if (RELU) { v0 = fmaxf(v0, 0.f); v1 = fmaxf(v1, 0.f); }
                float* cp = &C[(long)row*N + col];
                if (ACC) { v0 += cp[0]; v1 += cp[1]; }
                cp[0] = v0; cp[1] = v1;
            }
        }
    }
}

template<bool USE_BIAS, bool RELU, bool ACC>
__global__ __launch_bounds__(256, 2) void bf_gemm(
        const float* __restrict__ A, const float* __restrict__ B,
        const float* __restrict__ bias, float* __restrict__ C,
        int M, int N, int K) {
    gemm_body_bf<USE_BIAS, RELU, ACC>(A, B, bias, C, M, N, K,
                                      blockIdx.y * 128, blockIdx.x * 64);
}

// ---------------- Flash attention, bf16 mma + ldmatrix -------------------------
// CTA: 128 threads (4 warps), 128 queries x 64 keys per iteration.
// Qs/Ks: [row][dword]; Vs transposed [d][keyword]; Ps per-warp [32][keyword].
// Pad FLD=36: ldmatrix 8-row phases hit all 32 banks (rows stride 4 banks).
#define FLD 36
__global__ __launch_bounds__(128) void flash_mma(
        const float* __restrict__ q, const float* __restrict__ k,
        const float* __restrict__ v, float* __restrict__ o_out) {
    extern __shared__ uint32_t sm[];
    uint32_t* Qs = sm;                       // [128][FLD]
    uint32_t* Ks = Qs + 128*FLD;             // [64][FLD]
    uint32_t* Vs = Ks + 64*FLD;              // [64 d][FLD]
    uint32_t* Ps = Vs + 64*FLD;              // [4][32][FLD]

    int tid = threadIdx.x;
    int warp = tid >> 5, lane = tid & 31;
    int g = lane >> 2, t = lane & 3;
    int q0 = blockIdx.x * 128;
    int bh = blockIdx.y;
    int b = bh >> 3, h = bh & 7;
    long base = (long)b * SS;
    int hh = h * 64;
    uint32_t* Pw = Ps + warp * 32 * FLD;
    int wr = warp * 32;

    // ldmatrix x4 address components (computed once)
    int l15  = lane & 15;
    int roff = (lane & 16) >> 1;   // +8 rows for B matrices 2,3
    int coff = (lane & 8) >> 1;    // +4 kwords for B matrices 1,3
    int acoff = (lane & 16) >> 2;  // +4 kwords for A matrices 2,3

    // load Q tile (128 x 64 fp32 -> 128 x 32 words)
#pragma unroll
    for (int i = 0; i < 16; ++i) {
        int idx = tid + i*128;
        int r = idx >> 4, wq = (idx & 15) * 2;
        float4 vv = *reinterpret_cast<const float4*>(&q[(base + q0 + r)*DD + hh + wq*2]);
        uint32_t* p = &Qs[r*FLD + wq];
        p[0] = pk2(vv.x, vv.y); p[1] = pk2(vv.z, vv.w);
    }

    float mrow[2][2] = {{-INFINITY, -INFINITY}, {-INFINITY, -INFINITY}};
    float lrow[2][2] = {{0.f, 0.f}, {0.f, 0.f}};
    float o_acc[2][8][4];
#pragma unroll
    for (int mt = 0; mt < 2; ++mt)
#pragma unroll
        for (int nt = 0; nt < 8; ++nt)
#pragma unroll
            for (int j = 0; j < 4; ++j) o_acc[mt][nt][j] = 0.f;

    int vr = tid & 31;          // V keyword (keys 2vr, 2vr+1)
    int vcb = (tid >> 5) * 4;   // V d-col base, +16 per iteration

    for (int kb = 0; kb < SS/64; ++kb) {
        __syncthreads();
        int kbase = kb * 64;
        // K: row-major words
#pragma unroll
        for (int i = 0; i < 8; ++i) {
            int idx = tid + i*128;
            int r = idx >> 4, wq = (idx & 15) * 2;
            float4 kv = *reinterpret_cast<const float4*>(&k[(base + kbase + r)*DD + hh + wq*2]);
            uint32_t* p = &Ks[r*FLD + wq];
            p[0] = pk2(kv.x, kv.y); p[1] = pk2(kv.z, kv.w);
        }
        // V: transposed [d][keyword]
#pragma unroll
        for (int i = 0; i < 4; ++i) {
            int c4 = vcb + i*16;
            float4 v0 = *reinterpret_cast<const float4*>(&v[(base + kbase + 2*vr    )*DD + hh + c4]);
            float4 v1 = *reinterpret_cast<const float4*>(&v[(base + kbase + 2*vr + 1)*DD + hh + c4]);
            Vs[(c4 + 0)*FLD + vr] = pk2(v0.x, v1.x);
            Vs[(c4 + 1)*FLD + vr] = pk2(v0.y, v1.y);
            Vs[(c4 + 2)*FLD + vr] = pk2(v0.z, v1.z);
            Vs[(c4 + 3)*FLD + vr] = pk2(v0.w, v1.w);
        }
        __syncthreads();

        // S = Q K^T  (32 x 64 per warp), k-dim = d: 32 words, 4 k16 steps
        float s[2][8][4];
#pragma unroll
        for (int mt = 0; mt < 2; ++mt)
#pragma unroll
            for (int nt = 0; nt < 8; ++nt)
#pragma unroll
                for (int j = 0; j < 4; ++j) s[mt][nt][j] = 0.f;
#pragma unroll
        for (int ks = 0; ks < 4; ++ks) {
            int kk = ks * 8;
            uint32_t b0[8], b1[8];
#pragma unroll
            for (int np = 0; np < 4; ++np) {
                uint32_t addr = sptr(&Ks[(16*np + (lane & 7) + roff)*FLD + kk + coff]);
                ldsm_x4(b0[2*np], b1[2*np], b0[2*np+1], b1[2*np+1], addr);
            }
#pragma unroll
            for (int mt = 0; mt < 2; ++mt) {
                uint32_t a0, a1, a2, a3;
                uint32_t addr = sptr(&Qs[(wr + mt*16 + l15)*FLD + kk + acoff]);
                ldsm_x4(a0, a1, a2, a3, addr);
#pragma unroll
                for (int nt = 0; nt < 8; ++nt)
                    mma16(s[mt][nt], a0, a1, a2, a3, b0[nt], b1[nt]);
            }
        }

        // online softmax per m-tile; write P as packed bf16 words
#pragma unroll
        for (int mt = 0; mt < 2; ++mt) {
            float mx0 = -INFINITY, mx1 = -INFINITY;
#pragma unroll
            for (int nt = 0; nt < 8; ++nt) {
#pragma unroll
                for (int j = 0; j < 4; ++j) s[mt][nt][j] *= 0.125f;
                mx0 = fmaxf(mx0, fmaxf(s[mt][nt][0], s[mt][nt][1]));
                mx1 = fmaxf(mx1, fmaxf(s[mt][nt][2], s[mt][nt][3]));
            }
            mx0 = fmaxf(mx0, __shfl_xor_sync(0xffffffffu, mx0, 1));
            mx0 = fmaxf(mx0, __shfl_xor_sync(0xffffffffu, mx0, 2));
            mx1 = fmaxf(mx1, __shfl_xor_sync(0xffffffffu, mx1, 1));
            mx1 = fmaxf(mx1, __shfl_xor_sync(0xffffffffu, mx1, 2));
            float mn0 = fmaxf(mrow[mt][0], mx0), mn1 = fmaxf(mrow[mt][1], mx1);
            float al0 = __expf(mrow[mt][0] - mn0), al1 = __expf(mrow[mt][1] - mn1);

            float ps0 = 0.f, ps1 = 0.f;
            int prow = mt*16 + g;
#pragma unroll
            for (int nt = 0; nt < 8; ++nt) {
                float p0 = __expf(s[mt][nt][0] - mn0);
                float p1 = __expf(s[mt][nt][1] - mn0);
                float p2 = __expf(s[mt][nt][2] - mn1);
                float p3 = __expf(s[mt][nt][3] - mn1);
                ps0 += p0 + p1; ps1 += p2 + p3;
                int cw = nt*4 + t;
                Pw[(prow    )*FLD + cw] = pk2(p0, p1);
                Pw[(prow + 8)*FLD + cw] = pk2(p2, p3);
            }
            ps0 += __shfl_xor_sync(0xffffffffu, ps0, 1);
            ps0 += __shfl_xor_sync(0xffffffffu, ps0, 2);
            ps1 += __shfl_xor_sync(0xffffffffu, ps1, 1);
            ps1 += __shfl_xor_sync(0xffffffffu, ps1, 2);
            lrow[mt][0] = lrow[mt][0] * al0 + ps0;
            lrow[mt][1] = lrow[mt][1] * al1 + ps1;
            mrow[mt][0] = mn0; mrow[mt][1] = mn1;
#pragma unroll
            for (int nt = 0; nt < 8; ++nt) {
                o_acc[mt][nt][0] *= al0; o_acc[mt][nt][1] *= al0;
                o_acc[mt][nt][2] *= al1; o_acc[mt][nt][3] *= al1;
            }
        }
        __syncwarp();

        // O += P V  (k-dim = key: 32 words, 4 k16 steps; n-dim = d 64)
#pragma unroll
        for (int ks = 0; ks < 4; ++ks) {
            int kk = ks * 8;
            uint32_t b0[8], b1[8];
#pragma unroll
            for (int np = 0; np < 4; ++np) {
                uint32_t addr = sptr(&Vs[(16*np + (lane & 7) + roff)*FLD + kk + coff]);
                ldsm_x4(b0[2*np], b1[2*np], b0[2*np+1], b1[2*np+1], addr);
            }
#pragma unroll
            for (int mt = 0; mt < 2; ++mt) {
                uint32_t a0, a1, a2, a3;
                uint32_t addr = sptr(&Pw[(mt*16 + l15)*FLD + kk + acoff]);
                ldsm_x4(a0, a1, a2, a3, addr);
#pragma unroll
                for (int nt = 0; nt < 8; ++nt)
                    mma16(o_acc[mt][nt], a0, a1, a2, a3, b0[nt], b1[nt]);
            }
        }
        __syncwarp();
    }

#pragma unroll
    for (int mt = 0; mt < 2; ++mt) {
        float inv0 = 1.f / lrow[mt][0], inv1 = 1.f / lrow[mt][1];
#pragma unroll
        for (int nt = 0; nt < 8; ++nt) {
            int col = hh + nt*8 + 2*t;
            long r0 = (base + q0 + wr + mt*16 + g    )*DD + col;
            long r1 = (base + q0 + wr + mt*16 + g + 8)*DD + col;
            o_out[r0    ] = o_acc[mt][nt][0] * inv0;
            o_out[r0 + 1] = o_acc[mt][nt][1] * inv0;
            o_out[r1    ] = o_acc[mt][nt][2] * inv1;
            o_out[r1 + 1] = o_acc[mt][nt][3] * inv1;
        }
    }
}

// ---------------- row softmax over TV=1000 -------------------------------------
__global__ void softmax_out_kernel(float* __restrict__ x) {
    __shared__ float redA[4];
    __shared__ float redB[4];
    int row = blockIdx.x;
    int tid = threadIdx.x;
    float* xr = x + (long)row * TV;

    float vals[8];
    float mx = -INFINITY;
#pragma unroll
    for (int kq = 0; kq < 8; ++kq) {
        int i = tid + kq*128;
        if (i < TV) { vals[kq] = xr[i]; mx = fmaxf(mx, vals[kq]); }
        else vals[kq] = -INFINITY;
    }
#pragma unroll
    for (int o = 16; o > 0; o >>= 1) mx = fmaxf(mx, __shfl_xor_sync(0xffffffffu, mx, o));
    if ((tid & 31) == 0) redA[tid >> 5] = mx;
    __syncthreads();
    mx = fmaxf(fmaxf(redA[0], redA[1]), fmaxf(redA[2], redA[3]));

    float sum = 0.f;
#pragma unroll
    for (int kq = 0; kq < 8; ++kq) {
        int i = tid + kq*128;
        if (i < TV) { vals[kq] = expf(vals[kq] - mx); sum += vals[kq]; }
    }
#pragma unroll
    for (int o = 16; o > 0; o >>= 1) sum += __shfl_xor_sync(0xffffffffu, sum, o);
    if ((tid & 31) == 0) redB[tid >> 5] = sum;
    __syncthreads();
    sum = redB[0] + redB[1] + redB[2] + redB[3];
    float inv = 1.f / sum;
#pragma unroll
    for (int kq = 0; kq < 8; ++kq) {
        int i = tid + kq*128;
        if (i < TV) xr[i] = vals[kq] * inv;
    }
}

// ---------------- launch -------------------------------------------------------
extern "C" void kernel_launch(void* const* d_in, const int* in_sizes, int n_in,
                              void* d_out, int out_size) {
    const int*   ids   = (const int*)  d_in[0];
    const float* emb   = (const float*)d_in[2];
    const float* ln1_s = (const float*)d_in[3];
    const float* ln1_b = (const float*)d_in[4];
    const float* Wq    = (const float*)d_in[5];
    const float* Wk    = (const float*)d_in[6];
    const float* Wv    = (const float*)d_in[7];
    const float* Wo    = (const float*)d_in[8];
    const float* ln2_s = (const float*)d_in[9];
    const float* ln2_b = (const float*)d_in[10];
    const float* W1    = (const float*)d_in[11];
    const float* b1    = (const float*)d_in[12];
    const float* W2    = (const float*)d_in[13];
    const float* b2    = (const float*)d_in[14];
    const float* Wout  = (const float*)d_in[15];
    const float* bout  = (const float*)d_in[16];
    float* out = (float*)d_out;

    float *ph, *pa, *pqkv, *pt, *pf;
    cudaGetSymbolAddress((void**)&ph, g_h);
    cudaGetSymbolAddress((void**)&pa, g_a);
    cudaGetSymbolAddress((void**)&pqkv, g_qkv);
    cudaGetSymbolAddress((void**)&pt, g_t);
    cudaGetSymbolAddress((void**)&pf, g_f);
    float* pq = pqkv;
    float* pk = pqkv + (long)NT*DD;
    float* pv = pqkv + 2L*NT*DD;

    const int FA_SMEM = (128*FLD + 64*FLD + 64*FLD + 4*32*FLD) * 4;  // 55,296 B
    cudaFuncSetAttribute(flash_mma, cudaFuncAttributeMaxDynamicSharedMemorySize, FA_SMEM);

    embed_kernel<<<(NT*DD + 255)/256, 256>>>(ids, emb, ph);

    dim3 gProj((DD   + 63)/64, NT/128);          // (8, 32)  = 256 blocks
    dim3 gQKV ((DD   + 63)/64, NT/128, 3);       // 768 blocks
    dim3 gFF1 ((FFDIM+ 63)/64, NT/128);          // (32, 32) = 1024 blocks
    dim3 gOut ((TV   + 63)/64, NT/128);          // (16, 32) = 512 blocks

    for (int l = 0; l < NLAYER; ++l) {
        ln_kernel<<<NT, 128>>>(ph, ln1_s + l*DD, ln1_b + l*DD, pa);

        mma_gemm_qkv<<<gQKV, 256>>>(pa, Wq + (long)l*DD*DD, Wk + (long)l*DD*DD,
                                    Wv + (long)l*DD*DD, pqkv, NT, DD, DD);

        flash_mma<<<dim3(SS/128, BB*HH), 128, FA_SMEM>>>(pq, pk, pv, pt);

        mma_gemm<false,false,true><<<gProj, 256>>>(pt, Wo + (long)l*DD*DD, nullptr, ph, NT, DD, DD);

        ln_kernel<<<NT, 128>>>(ph, ln2_s + l*DD, ln2_b + l*DD, pa);

        // FFN in bf16 (calculated gamble: predicted rel_err ~6e-4)
        bf_gemm<true,true,false><<<gFF1, 256>>>(pa, W1 + (long)l*DD*FFDIM, b1 + (long)l*FFDIM, pf, NT, FFDIM, DD);
        bf_gemm<true,false,true><<<gProj, 256>>>(pf, W2 + (long)l*FFDIM*DD, b2 + (long)l*DD, ph, NT, DD, FFDIM);
    }

    mma_gemm<true,false,false><<<gOut, 256>>>(ph, Wout, bout, out, NT, TV, DD);
    softmax_out_kernel<<<NT, 128>>>(out);
}

// round 16
// speedup vs baseline: 1.5999x; 1.5999x over previous
#include <cuda_runtime.h>
#include <cuda_bf16.h>
#include <math.h>
#include <stdint.h>

// Problem constants
#define BB 2
#define SS 2048
#define DD 512
#define HH 8
#define NT (BB*SS)     // 4096 tokens
#define FFDIM 2048
#define TV 1000
#define NLAYER 2

// ---------------- scratch ------------------------------------------------------
__device__ float g_h[NT*DD];
__device__ float g_a[NT*DD];
__device__ float g_qkv[3][NT*DD];
__device__ float g_t[NT*DD];
__device__ float g_f[NT*FFDIM];

// ---------------- mma helpers --------------------------------------------------
__device__ __forceinline__ void mma8(float* c,
                                     uint32_t a0, uint32_t a1, uint32_t a2, uint32_t a3,
                                     uint32_t b0, uint32_t b1) {
    asm volatile("mma.sync.aligned.m16n8k8.row.col.f32.tf32.tf32.f32 "
                 "{%0,%1,%2,%3}, {%4,%5,%6,%7}, {%8,%9}, {%0,%1,%2,%3};"
                 : "+f"(c[0]), "+f"(c[1]), "+f"(c[2]), "+f"(c[3])
                 : "r"(a0), "r"(a1), "r"(a2), "r"(a3), "r"(b0), "r"(b1));
}
__device__ __forceinline__ uint32_t pk2(float lo, float hi) {
    uint32_t r;
    asm("cvt.rn.bf16x2.f32 %0, %1, %2;" : "=r"(r) : "f"(hi), "f"(lo));
    return r;
}
__device__ __forceinline__ void mma16(float* c,
                                      uint32_t a0, uint32_t a1, uint32_t a2, uint32_t a3,
                                      uint32_t b0, uint32_t b1) {
    asm volatile("mma.sync.aligned.m16n8k16.row.col.f32.bf16.bf16.f32 "
                 "{%0,%1,%2,%3}, {%4,%5,%6,%7}, {%8,%9}, {%0,%1,%2,%3};"
                 : "+f"(c[0]), "+f"(c[1]), "+f"(c[2]), "+f"(c[3])
                 : "r"(a0), "r"(a1), "r"(a2), "r"(a3), "r"(b0), "r"(b1));
}
__device__ __forceinline__ uint32_t sptr(const void* p) {
    return (uint32_t)__cvta_generic_to_shared(p);
}
__device__ __forceinline__ void cpa16(uint32_t dst, const void* src) {
    asm volatile("cp.async.cg.shared.global [%0], [%1], 16;" :: "r"(dst), "l"(src));
}
__device__ __forceinline__ void cpa4(uint32_t dst, const void* src) {
    asm volatile("cp.async.ca.shared.global [%0], [%1], 4;" :: "r"(dst), "l"(src));
}
__device__ __forceinline__ void sts_zero(uint32_t dst) {
    asm volatile("st.shared.b32 [%0], %1;" :: "r"(dst), "r"(0u));
}
__device__ __forceinline__ void cpa_commit() {
    asm volatile("cp.async.commit_group;" ::: "memory");
}
template<int N>
__device__ __forceinline__ void cpa_wait() {
    asm volatile("cp.async.wait_group %0;" :: "n"(N) : "memory");
}

// ---------------- embedding + sinusoidal positional ---------------------------
__global__ void embed_kernel(const int* __restrict__ ids,
                             const float* __restrict__ emb,
                             float* __restrict__ h) {
    int idx = blockIdx.x * blockDim.x + threadIdx.x;
    if (idx >= NT*DD) return;
    int d   = idx & (DD-1);
    int tok = idx >> 9;
    int s   = tok & (SS-1);
    int id  = ids[tok];

    double pos;
    if (d < DD/2) {
        double inv = exp(-(2.0*d/(double)DD) * log(10000.0));
        pos = sin((double)s * inv);
    } else {
        int i = d - DD/2;
        double inv = exp(-(2.0*i/(double)DD) * log(10000.0));
        pos = cos((double)s * inv);
    }
    h[idx] = emb[id*DD + d] + (float)pos;
}

// ---------------- LayerNorm ----------------------------------------------------
__global__ void ln_kernel(const float* __restrict__ x,
                          const float* __restrict__ sc,
                          const float* __restrict__ bi,
                          float* __restrict__ y) {
    __shared__ float redA[4];
    __shared__ float redB[4];
    int row = blockIdx.x;
    int tid = threadIdx.x;
    const float* xr = x + row*DD;

    float v[4];
    float s = 0.f;
#pragma unroll
    for (int i = 0; i < 4; ++i) { v[i] = xr[tid + i*128]; s += v[i]; }
#pragma unroll
    for (int o = 16; o > 0; o >>= 1) s += __shfl_xor_sync(0xffffffffu, s, o);
    if ((tid & 31) == 0) redA[tid >> 5] = s;
    __syncthreads();
    float mean = (redA[0] + redA[1] + redA[2] + redA[3]) * (1.f/DD);

    float vs = 0.f;
#pragma unroll
    for (int i = 0; i < 4; ++i) { float d0 = v[i] - mean; vs += d0*d0; }
#pragma unroll
    for (int o = 16; o > 0; o >>= 1) vs += __shfl_xor_sync(0xffffffffu, vs, o);
    if ((tid & 31) == 0) redB[tid >> 5] = vs;
    __syncthreads();
    float var = (redB[0] + redB[1] + redB[2] + redB[3]) * (1.f/DD);
    float inv = rsqrtf(var + 1e-3f);

#pragma unroll
    for (int i = 0; i < 4; ++i) {
        int d0 = tid + i*128;
        y[row*DD + d0] = (v[i] - mean) * inv * sc[d0] + bi[d0];
    }
}

// ---------------- tf32 GEMM, cp.async 3-stage pipeline -------------------------
// C[M,N] (=/+=) op(A[M,K] @ B[K,N] + bias). Row-major fp32.
// BM=128 BN=64 BK=32. 256 threads = 8 warps (4M x 2N); warp tile 32x32.
// smem holds raw fp32; mma consumes the bits directly (HW truncates to tf32).
#define GLDA 36
#define GLDB 68
#define STAGE_W (128*GLDA + 32*GLDB)   // 6784 words per stage
#define NSTAGE 3
#define GEMM_SMEM (NSTAGE*STAGE_W*4)   // 81,408 B

template<bool USE_BIAS, bool RELU, bool ACC, bool NGUARD>
__device__ __forceinline__ void gemm_body(
        const float* __restrict__ A, const float* __restrict__ B,
        const float* __restrict__ bias, float* __restrict__ C,
        int M, int N, int K, int m0, int n0) {
    extern __shared__ uint32_t dyn[];
    int tid = threadIdx.x;
    int warp = tid >> 5, lane = tid & 31;
    int wm = warp >> 1, wn = warp & 1;
    int g = lane >> 2, t = lane & 3;

    int ar = tid >> 3,  akq = (tid & 7) * 4;   // A: rows ar+32i, kwords akq..+3
    int br = tid >> 4,  bnq = (tid & 15) * 4;  // B: rows br+16i, cols bnq..+3

    uint32_t sm0 = sptr(dyn);
    int nk = K >> 5;

    auto load_stage = [&](int it) {
        int k0 = it << 5;
        uint32_t sa = sm0 + (it % NSTAGE) * (STAGE_W * 4);
        uint32_t sb = sa + 128*GLDA*4;
#pragma unroll
        for (int i = 0; i < 4; ++i)
            cpa16(sa + ((ar + i*32)*GLDA + akq)*4,
                  &A[(long)(m0 + ar + i*32)*K + k0 + akq]);
        int col = n0 + bnq;
#pragma unroll
        for (int i = 0; i < 2; ++i) {
            long rowoff = (long)(k0 + br + i*16)*N;
            uint32_t dst = sb + ((br + i*16)*GLDB + bnq)*4;
            if (!NGUARD || col + 3 < N) {
                cpa16(dst, &B[rowoff + col]);
            } else {
#pragma unroll
                for (int j = 0; j < 4; ++j) {
                    if (col + j < N) cpa4(dst + 4*j, &B[rowoff + col + j]);
                    else             sts_zero(dst + 4*j);
                }
            }
        }
        cpa_commit();
    };

    float c[2][4][4];
#pragma unroll
    for (int mt = 0; mt < 2; ++mt)
#pragma unroll
        for (int nt = 0; nt < 4; ++nt)
#pragma unroll
            for (int j = 0; j < 4; ++j) c[mt][nt][j] = 0.f;

    load_stage(0);
    load_stage(1);
    cpa_wait<1>();
    __syncthreads();

    for (int it = 0; it < nk; ++it) {
        const uint32_t* As = dyn + (it % NSTAGE) * STAGE_W;
        const uint32_t* Bs = As + 128*GLDA;

        bool more = (it + 2 < nk);
        if (more) load_stage(it + 2);

        int rbw = wm*32, nbw = wn*32;
#pragma unroll
        for (int ks = 0; ks < 4; ++ks) {
            int kk = ks * 8;
            uint32_t a[2][4], b[4][2];
#pragma unroll
            for (int mt = 0; mt < 2; ++mt) {
                int rb = rbw + mt*16;
                a[mt][0] = As[(rb + g    )*GLDA + kk + t];
                a[mt][1] = As[(rb + g + 8)*GLDA + kk + t];
                a[mt][2] = As[(rb + g    )*GLDA + kk + t + 4];
                a[mt][3] = As[(rb + g + 8)*GLDA + kk + t + 4];
            }
#pragma unroll
            for (int nt = 0; nt < 4; ++nt) {
                int nb = nbw + nt*8;
                b[nt][0] = Bs[(kk + t    )*GLDB + nb + g];
                b[nt][1] = Bs[(kk + t + 4)*GLDB + nb + g];
            }
#pragma unroll
            for (int mt = 0; mt < 2; ++mt)
#pragma unroll
                for (int nt = 0; nt < 4; ++nt)
                    mma8(c[mt][nt], a[mt][0], a[mt][1], a[mt][2], a[mt][3],
                         b[nt][0], b[nt][1]);
        }

        if (more)       cpa_wait<1>();
        else            cpa_wait<0>();
        __syncthreads();
    }

#pragma unroll
    for (int mt = 0; mt < 2; ++mt) {
#pragma unroll
        for (int nt = 0; nt < 4; ++nt) {
            int row0 = m0 + wm*32 + mt*16 + g;
            int col  = n0 + wn*32 + nt*8 + 2*t;
            if (!NGUARD || col < N) {
                float b0 = 0.f, b1 = 0.f;
                if (USE_BIAS) { b0 = bias[col]; b1 = bias[col + 1]; }
#pragma unroll
                for (int half = 0; half < 2; ++half) {
                    int row = row0 + half*8;
                    float v0 = c[mt][nt][half*2 + 0] + b0;
                    float v1 = c[mt][nt][half*2 + 1] + b1;
                    if (RELU) { v0 = fmaxf(v0, 0.f); v1 = fmaxf(v1, 0.f); }
                    float* cp = &C[(long)row*N + col];
                    if (ACC) { v0 += cp[0]; v1 += cp[1]; }
                    cp[0] = v0; cp[1] = v1;
                }
            }
        }
    }
}

template<bool USE_BIAS, bool RELU, bool ACC, bool NGUARD>
__global__ __launch_bounds__(256, 2) void mma_gemm(
        const float* __restrict__ A, const float* __restrict__ B,
        const float* __restrict__ bias, float* __restrict__ C,
        int M, int N, int K) {
    gemm_body<USE_BIAS, RELU, ACC, NGUARD>(A, B, bias, C, M, N, K,
                                           blockIdx.y * 128, blockIdx.x * 64);
}

__global__ __launch_bounds__(256, 2) void mma_gemm_qkv(
        const float* __restrict__ A,
        const float* __restrict__ Bq, const float* __restrict__ Bk,
        const float* __restrict__ Bv, float* __restrict__ Cbase,
        int M, int N, int K) {
    int z = blockIdx.z;
    const float* B = (z == 0) ? Bq : (z == 1) ? Bk : Bv;
    float* C = Cbase + (long)z * NT * DD;
    gemm_body<false, false, false, false>(A, B, nullptr, C, M, N, K,
                                          blockIdx.y * 128, blockIdx.x * 64);
}

// ---------------- Flash attention, bf16 mma (round-12 proven) ------------------
// CTA: 128 threads (4 warps), 128 queries x 64 keys per iteration.
// Qs/Ks: [row][dword]; Vs transposed [d][keyword]; Ps per-warp [32][keyword].
#define FLD 36
__global__ __launch_bounds__(128) void flash_mma(
        const float* __restrict__ q, const float* __restrict__ k,
        const float* __restrict__ v, float* __restrict__ o_out) {
    extern __shared__ uint32_t sm[];
    uint32_t* Qs = sm;                       // [128][FLD]
    uint32_t* Ks = Qs + 128*FLD;             // [64][FLD]
    uint32_t* Vs = Ks + 64*FLD;              // [64 d][FLD]
    uint32_t* Ps = Vs + 64*FLD;              // [4][32][FLD]

    int tid = threadIdx.x;
    int warp = tid >> 5, lane = tid & 31;
    int g = lane >> 2, t = lane & 3;
    int q0 = blockIdx.x * 128;
    int bh = blockIdx.y;
    int b = bh >> 3, h = bh & 7;
    long base = (long)b * SS;
    int hh = h * 64;
    uint32_t* Pw = Ps + warp * 32 * FLD;
    int wr = warp * 32;

    // load Q tile (128 x 64 fp32 -> 128 x 32 words)
#pragma unroll
    for (int i = 0; i < 16; ++i) {
        int idx = tid + i*128;
        int r = idx >> 4, wq = (idx & 15) * 2;
        float4 vv = *reinterpret_cast<const float4*>(&q[(base + q0 + r)*DD + hh + wq*2]);
        uint32_t* p = &Qs[r*FLD + wq];
        p[0] = pk2(vv.x, vv.y); p[1] = pk2(vv.z, vv.w);
    }

    float mrow[2][2] = {{-INFINITY, -INFINITY}, {-INFINITY, -INFINITY}};
    float lrow[2][2] = {{0.f, 0.f}, {0.f, 0.f}};
    float o_acc[2][8][4];
#pragma unroll
    for (int mt = 0; mt < 2; ++mt)
#pragma unroll
        for (int nt = 0; nt < 8; ++nt)
#pragma unroll
            for (int j = 0; j < 4; ++j) o_acc[mt][nt][j] = 0.f;

    int vr = tid & 31;          // V keyword (keys 2vr, 2vr+1)
    int vcb = (tid >> 5) * 4;   // V d-col base, +16 per iteration

    for (int kb = 0; kb < SS/64; ++kb) {
        __syncthreads();
        int kbase = kb * 64;
#pragma unroll
        for (int i = 0; i < 8; ++i) {
            int idx = tid + i*128;
            int r = idx >> 4, wq = (idx & 15) * 2;
            float4 kv = *reinterpret_cast<const float4*>(&k[(base + kbase + r)*DD + hh + wq*2]);
            uint32_t* p = &Ks[r*FLD + wq];
            p[0] = pk2(kv.x, kv.y); p[1] = pk2(kv.z, kv.w);
        }
#pragma unroll
        for (int i = 0; i < 4; ++i) {
            int c4 = vcb + i*16;
            float4 v0 = *reinterpret_cast<const float4*>(&v[(base + kbase + 2*vr    )*DD + hh + c4]);
            float4 v1 = *reinterpret_cast<const float4*>(&v[(base + kbase + 2*vr + 1)*DD + hh + c4]);
            Vs[(c4 + 0)*FLD + vr] = pk2(v0.x, v1.x);
            Vs[(c4 + 1)*FLD + vr] = pk2(v0.y, v1.y);
            Vs[(c4 + 2)*FLD + vr] = pk2(v0.z, v1.z);
            Vs[(c4 + 3)*FLD + vr] = pk2(v0.w, v1.w);
        }
        __syncthreads();

        // S = Q K^T  (32 x 64 per warp), k-dim = d: 32 words, 4 k16 steps
        float s[2][8][4];
#pragma unroll
        for (int mt = 0; mt < 2; ++mt)
#pragma unroll
            for (int nt = 0; nt < 8; ++nt)
#pragma unroll
                for (int j = 0; j < 4; ++j) s[mt][nt][j] = 0.f;
#pragma unroll
        for (int ks = 0; ks < 4; ++ks) {
            int kk = ks * 8;
            uint32_t b0[8], b1[8];
#pragma unroll
            for (int nt = 0; nt < 8; ++nt) {
                b0[nt] = Ks[(nt*8 + g)*FLD + kk + t];
                b1[nt] = Ks[(nt*8 + g)*FLD + kk + t + 4];
            }
#pragma unroll
            for (int mt = 0; mt < 2; ++mt) {
                int rbm = wr + mt*16;
                uint32_t a0 = Qs[(rbm + g    )*FLD + kk + t];
                uint32_t a1 = Qs[(rbm + g + 8)*FLD + kk + t];
                uint32_t a2 = Qs[(rbm + g    )*FLD + kk + t + 4];
                uint32_t a3 = Qs[(rbm + g + 8)*FLD + kk + t + 4];
#pragma unroll
                for (int nt = 0; nt < 8; ++nt)
                    mma16(s[mt][nt], a0, a1, a2, a3, b0[nt], b1[nt]);
            }
        }

        // online softmax per m-tile; write P as packed bf16 words
#pragma unroll
        for (int mt = 0; mt < 2; ++mt) {
            float mx0 = -INFINITY, mx1 = -INFINITY;
#pragma unroll
            for (int nt = 0; nt < 8; ++nt) {
#pragma unroll
                for (int j = 0; j < 4; ++j) s[mt][nt][j] *= 0.125f;
                mx0 = fmaxf(mx0, fmaxf(s[mt][nt][0], s[mt][nt][1]));
                mx1 = fmaxf(mx1, fmaxf(s[mt][nt][2], s[mt][nt][3]));
            }
            mx0 = fmaxf(mx0, __shfl_xor_sync(0xffffffffu, mx0, 1));
            mx0 = fmaxf(mx0, __shfl_xor_sync(0xffffffffu, mx0, 2));
            mx1 = fmaxf(mx1, __shfl_xor_sync(0xffffffffu, mx1, 1));
            mx1 = fmaxf(mx1, __shfl_xor_sync(0xffffffffu, mx1, 2));
            float mn0 = fmaxf(mrow[mt][0], mx0), mn1 = fmaxf(mrow[mt][1], mx1);
            float al0 = __expf(mrow[mt][0] - mn0), al1 = __expf(mrow[mt][1] - mn1);

            float ps0 = 0.f, ps1 = 0.f;
            int prow = mt*16 + g;
#pragma unroll
            for (int nt = 0; nt < 8; ++nt) {
                float p0 = __expf(s[mt][nt][0] - mn0);
                float p1 = __expf(s[mt][nt][1] - mn0);
                float p2 = __expf(s[mt][nt][2] - mn1);
                float p3 = __expf(s[mt][nt][3] - mn1);
                ps0 += p0 + p1; ps1 += p2 + p3;
                int cw = nt*4 + t;
                Pw[(prow    )*FLD + cw] = pk2(p0, p1);
                Pw[(prow + 8)*FLD + cw] = pk2(p2, p3);
            }
            ps0 += __shfl_xor_sync(0xffffffffu, ps0, 1);
            ps0 += __shfl_xor_sync(0xffffffffu, ps0, 2);
            ps1 += __shfl_xor_sync(0xffffffffu, ps1, 1);
            ps1 += __shfl_xor_sync(0xffffffffu, ps1, 2);
            lrow[mt][0] = lrow[mt][0] * al0 + ps0;
            lrow[mt][1] = lrow[mt][1] * al1 + ps1;
            mrow[mt][0] = mn0; mrow[mt][1] = mn1;
#pragma unroll
            for (int nt = 0; nt < 8; ++nt) {
                o_acc[mt][nt][0] *= al0; o_acc[mt][nt][1] *= al0;
                o_acc[mt][nt][2] *= al1; o_acc[mt][nt][3] *= al1;
            }
        }
        __syncwarp();

        // O += P V  (k-dim = key: 32 words, 4 k16 steps; n-dim = d 64)
#pragma unroll
        for (int ks = 0; ks < 4; ++ks) {
            int kk = ks * 8;
            uint32_t b0[8], b1[8];
#pragma unroll
            for (int nt = 0; nt < 8; ++nt) {
                b0[nt] = Vs[(nt*8 + g)*FLD + kk + t];
                b1[nt] = Vs[(nt*8 + g)*FLD + kk + t + 4];
            }
#pragma unroll
            for (int mt = 0; mt < 2; ++mt) {
                int prow = mt*16;
                uint32_t a0 = Pw[(prow + g    )*FLD + kk + t];
                uint32_t a1 = Pw[(prow + g + 8)*FLD + kk + t];
                uint32_t a2 = Pw[(prow + g    )*FLD + kk + t + 4];
                uint32_t a3 = Pw[(prow + g + 8)*FLD + kk + t + 4];
#pragma unroll
                for (int nt = 0; nt < 8; ++nt)
                    mma16(o_acc[mt][nt], a0, a1, a2, a3, b0[nt], b1[nt]);
            }
        }
        __syncwarp();
    }

#pragma unroll
    for (int mt = 0; mt < 2; ++mt) {
        float inv0 = 1.f / lrow[mt][0], inv1 = 1.f / lrow[mt][1];
#pragma unroll
        for (int nt = 0; nt < 8; ++nt) {
            int col = hh + nt*8 + 2*t;
            long r0 = (base + q0 + wr + mt*16 + g    )*DD + col;
            long r1 = (base + q0 + wr + mt*16 + g + 8)*DD + col;
            o_out[r0    ] = o_acc[mt][nt][0] * inv0;
            o_out[r0 + 1] = o_acc[mt][nt][1] * inv0;
            o_out[r1    ] = o_acc[mt][nt][2] * inv1;
            o_out[r1 + 1] = o_acc[mt][nt][3] * inv1;
        }
    }
}

// ---------------- row softmax over TV=1000 -------------------------------------
__global__ void softmax_out_kernel(float* __restrict__ x) {
    __shared__ float redA[4];
    __shared__ float redB[4];
    int row = blockIdx.x;
    int tid = threadIdx.x;
    float* xr = x + (long)row * TV;

    float vals[8];
    float mx = -INFINITY;
#pragma unroll
    for (int kq = 0; kq < 8; ++kq) {
        int i = tid + kq*128;
        if (i < TV) { vals[kq] = xr[i]; mx = fmaxf(mx, vals[kq]); }
        else vals[kq] = -INFINITY;
    }
#pragma unroll
    for (int o = 16; o > 0; o >>= 1) mx = fmaxf(mx, __shfl_xor_sync(0xffffffffu, mx, o));
    if ((tid & 31) == 0) redA[tid >> 5] = mx;
    __syncthreads();
    mx = fmaxf(fmaxf(redA[0], redA[1]), fmaxf(redA[2], redA[3]));

    float sum = 0.f;
#pragma unroll
    for (int kq = 0; kq < 8; ++kq) {
        int i = tid + kq*128;
        if (i < TV) { vals[kq] = expf(vals[kq] - mx); sum += vals[kq]; }
    }
#pragma unroll
    for (int o = 16; o > 0; o >>= 1) sum += __shfl_xor_sync(0xffffffffu, sum, o);
    if ((tid & 31) == 0) redB[tid >> 5] = sum;
    __syncthreads();
    sum = redB[0] + redB[1] + redB[2] + redB[3];
    float inv = 1.f / sum;
#pragma unroll
    for (int kq = 0; kq < 8; ++kq) {
        int i = tid + kq*128;
        if (i < TV) xr[i] = vals[kq] * inv;
    }
}

// ---------------- launch -------------------------------------------------------
extern "C" void kernel_launch(void* const* d_in, const int* in_sizes, int n_in,
                              void* d_out, int out_size) {
    const int*   ids   = (const int*)  d_in[0];
    const float* emb   = (const float*)d_in[2];
    const float* ln1_s = (const float*)d_in[3];
    const float* ln1_b = (const float*)d_in[4];
    const float* Wq    = (const float*)d_in[5];
    const float* Wk    = (const float*)d_in[6];
    const float* Wv    = (const float*)d_in[7];
    const float* Wo    = (const float*)d_in[8];
    const float* ln2_s = (const float*)d_in[9];
    const float* ln2_b = (const float*)d_in[10];
    const float* W1    = (const float*)d_in[11];
    const float* b1    = (const float*)d_in[12];
    const float* W2    = (const float*)d_in[13];
    const float* b2    = (const float*)d_in[14];
    const float* Wout  = (const float*)d_in[15];
    const float* bout  = (const float*)d_in[16];
    float* out = (float*)d_out;

    float *ph, *pa, *pqkv, *pt, *pf;
    cudaGetSymbolAddress((void**)&ph, g_h);
    cudaGetSymbolAddress((void**)&pa, g_a);
    cudaGetSymbolAddress((void**)&pqkv, g_qkv);
    cudaGetSymbolAddress((void**)&pt, g_t);
    cudaGetSymbolAddress((void**)&pf, g_f);
    float* pq = pqkv;
    float* pk = pqkv + (long)NT*DD;
    float* pv = pqkv + 2L*NT*DD;

    const int FA_SMEM = (128*FLD + 64*FLD + 64*FLD + 4*32*FLD) * 4;  // 55,296 B
    cudaFuncSetAttribute(flash_mma, cudaFuncAttributeMaxDynamicSharedMemorySize, FA_SMEM);
    cudaFuncSetAttribute(mma_gemm<false,false,false,false>, cudaFuncAttributeMaxDynamicSharedMemorySize, GEMM_SMEM);
    cudaFuncSetAttribute(mma_gemm<false,false,true ,false>, cudaFuncAttributeMaxDynamicSharedMemorySize, GEMM_SMEM);
    cudaFuncSetAttribute(mma_gemm<true ,true ,false,false>, cudaFuncAttributeMaxDynamicSharedMemorySize, GEMM_SMEM);
    cudaFuncSetAttribute(mma_gemm<true ,false,true ,false>, cudaFuncAttributeMaxDynamicSharedMemorySize, GEMM_SMEM);
    cudaFuncSetAttribute(mma_gemm<true ,false,false,true >, cudaFuncAttributeMaxDynamicSharedMemorySize, GEMM_SMEM);
    cudaFuncSetAttribute(mma_gemm_qkv, cudaFuncAttributeMaxDynamicSharedMemorySize, GEMM_SMEM);

    embed_kernel<<<(NT*DD + 255)/256, 256>>>(ids, emb, ph);

    dim3 gProj((DD   + 63)/64, NT/128);          // (8, 32)  = 256 blocks
    dim3 gQKV ((DD   + 63)/64, NT/128, 3);       // 768 blocks
    dim3 gFF1 ((FFDIM+ 63)/64, NT/128);          // (32, 32) = 1024 blocks
    dim3 gOut ((TV   + 63)/64, NT/128);          // (16, 32) = 512 blocks

    for (int l = 0; l < NLAYER; ++l) {
        ln_kernel<<<NT, 128>>>(ph, ln1_s + l*DD, ln1_b + l*DD, pa);

        mma_gemm_qkv<<<gQKV, 256, GEMM_SMEM>>>(pa, Wq + (long)l*DD*DD, Wk + (long)l*DD*DD,
                                               Wv + (long)l*DD*DD, pqkv, NT, DD, DD);

        flash_mma<<<dim3(SS/128, BB*HH), 128, FA_SMEM>>>(pq, pk, pv, pt);

        mma_gemm<false,false,true,false><<<gProj, 256, GEMM_SMEM>>>(pt, Wo + (long)l*DD*DD, nullptr, ph, NT, DD, DD);

        ln_kernel<<<NT, 128>>>(ph, ln2_s + l*DD, ln2_b + l*DD, pa);

        mma_gemm<true,true,false,false><<<gFF1, 256, GEMM_SMEM>>>(pa, W1 + (long)l*DD*FFDIM, b1 + (long)l*FFDIM, pf, NT, FFDIM, DD);
        mma_gemm<true,false,true,false><<<gProj, 256, GEMM_SMEM>>>(pf, W2 + (long)l*FFDIM*DD, b2 + (long)l*DD, ph, NT, DD, FFDIM);
    }

    mma_gemm<true,false,false,true><<<gOut, 256, GEMM_SMEM>>>(ph, Wout, bout, out, NT, TV, DD);
    softmax_out_kernel<<<NT, 128>>>(out);
}